// round 4
// baseline (speedup 1.0000x reference)
#include <cuda_runtime.h>
#include <cuda_fp16.h>
#include <cstdint>
#include <cstddef>

#define DINLINE __device__ __forceinline__

// =====================================================================
// out[m][n] = sum_k x[m][k] * h[(n-k) & 127],   h = Re(ifft(b))
// GEMM: A = x tile [128 rows x 128 k] (fp16 hi/lo split),
//       B = F[n][k] = h[(n-k)&127]  (fp16, static)
// mma.sync.aligned.m16n8k16.row.col.f32.f16.f16.f32
// 2-pass split: out = xh*hh + xl*hh  (error ~2^-12 from fp16(h) only)
// =====================================================================

static constexpr int D = 128;
static constexpr int TILE_M = 128;
// padded fp16 row stride: 136 halfs = 272 bytes (conflict-free LDS)
static constexpr int RS = 136;
static constexpr int TILE_BYTES = 128 * RS * 2;     // 34816
static constexpr int F_OFF  = 0;
static constexpr int XH_OFF = TILE_BYTES;           // 34816
static constexpr int XL_OFF = 2 * TILE_BYTES;       // 69632
static constexpr int SMEM_TOTAL = 3 * TILE_BYTES;   // 104448  (fits 2 CTAs/SM)

__device__ unsigned short g_h[128];   // fp16 bits of h

// ======================= Prep kernel: h = Re(ifft(b)) =======================

__global__ void __launch_bounds__(128) fourier_prep(const float* __restrict__ br,
                                                    const float* __restrict__ bi) {
    __shared__ float ct[128], st[128], sbr[128], sbi[128];
    int t = threadIdx.x;
    float ang = (float)t * (6.28318530717958647692f / 128.0f);
    float s, c;
    sincosf(ang, &s, &c);
    ct[t] = c; st[t] = s;
    sbr[t] = br[t]; sbi[t] = bi[t];
    __syncthreads();
    float acc = 0.0f;
    #pragma unroll 8
    for (int k = 0; k < 128; k++) {
        int idx = (k * t) & 127;             // exact integer angle reduction
        acc = fmaf(sbr[k], ct[idx], acc);
        acc = fmaf(-sbi[k], st[idx], acc);
    }
    acc *= (1.0f / 128.0f);
    g_h[t] = __half_as_ushort(__float2half_rn(acc));
}

// ======================= mma.sync wrapper =======================

DINLINE void mma16816(float* d, uint32_t a0, uint32_t a1, uint32_t a2, uint32_t a3,
                      uint32_t b0, uint32_t b1) {
    asm volatile(
        "mma.sync.aligned.m16n8k16.row.col.f32.f16.f16.f32 "
        "{%0,%1,%2,%3}, {%4,%5,%6,%7}, {%8,%9}, {%0,%1,%2,%3};"
        : "+f"(d[0]), "+f"(d[1]), "+f"(d[2]), "+f"(d[3])
        : "r"(a0), "r"(a1), "r"(a2), "r"(a3), "r"(b0), "r"(b1));
}

DINLINE uint32_t lds_u32(const __half* p) {
    return *reinterpret_cast<const uint32_t*>(p);
}

// ======================= Main kernel =======================

__global__ void __launch_bounds__(256, 2)
fourier_main(const float* __restrict__ x, float* __restrict__ out) {
    extern __shared__ char smem[];
    __half* F  = reinterpret_cast<__half*>(smem + F_OFF);
    __half* XH = reinterpret_cast<__half*>(smem + XH_OFF);
    __half* XL = reinterpret_cast<__half*>(smem + XL_OFF);

    const int tid  = threadIdx.x;
    const int warp = tid >> 5;
    const int lane = tid & 31;
    const int tile = blockIdx.x;

    // ---- issue all 16 x-tile LDG.128 up front (max MLP under DRAM latency) ----
    const float4* src = reinterpret_cast<const float4*>(x) + (size_t)tile * 4096;
    float4 v[16];
    #pragma unroll
    for (int it = 0; it < 16; it++)
        v[it] = __ldcs(src + it * 256 + tid);

    // ---- build filter tile F[n][k] = h[(n-k)&127] while loads are in flight ----
    #pragma unroll
    for (int idx = tid; idx < 128 * 64; idx += 256) {
        int n  = idx >> 6;
        int k  = (idx & 63) << 1;
        uint32_t w = (uint32_t)g_h[(n - k) & 127]
                   | ((uint32_t)g_h[(n - k - 1) & 127] << 16);
        *reinterpret_cast<uint32_t*>(F + n * RS + k) = w;
    }

    // ---- convert x to fp16 hi/lo, store to smem ----
    #pragma unroll
    for (int it = 0; it < 16; it++) {
        int i4 = it * 256 + tid;
        int row = i4 >> 5;              // 32 float4 per 128-float row
        int col = (i4 & 31) << 2;
        __half h0 = __float2half_rn(v[it].x);
        __half h1 = __float2half_rn(v[it].y);
        __half h2 = __float2half_rn(v[it].z);
        __half h3 = __float2half_rn(v[it].w);
        __half l0 = __float2half_rn(v[it].x - __half2float(h0));
        __half l1 = __float2half_rn(v[it].y - __half2float(h1));
        __half l2 = __float2half_rn(v[it].z - __half2float(h2));
        __half l3 = __float2half_rn(v[it].w - __half2float(h3));
        __half2* ph = reinterpret_cast<__half2*>(XH + row * RS + col);
        __half2* pl = reinterpret_cast<__half2*>(XL + row * RS + col);
        ph[0] = __halves2half2(h0, h1);
        ph[1] = __halves2half2(h2, h3);
        pl[0] = __halves2half2(l0, l1);
        pl[1] = __halves2half2(l2, l3);
    }
    __syncthreads();

    // ---- mma: each warp computes rows [warp*16, warp*16+16) x all 128 cols ----
    const int g  = lane >> 2;          // 0..7
    const int tg = lane & 3;           // 0..3

    float acc[16][4];
    #pragma unroll
    for (int nb = 0; nb < 16; nb++)
        #pragma unroll
        for (int q = 0; q < 4; q++) acc[nb][q] = 0.0f;

    const __half* ah_base = XH + (warp * 16 + g) * RS;
    const __half* al_base = XL + (warp * 16 + g) * RS;

    #pragma unroll
    for (int ks = 0; ks < 8; ks++) {
        const int kc = ks * 16 + 2 * tg;
        uint32_t ah0 = lds_u32(ah_base + kc);
        uint32_t ah1 = lds_u32(ah_base + 8 * RS + kc);
        uint32_t ah2 = lds_u32(ah_base + kc + 8);
        uint32_t ah3 = lds_u32(ah_base + 8 * RS + kc + 8);
        uint32_t al0 = lds_u32(al_base + kc);
        uint32_t al1 = lds_u32(al_base + 8 * RS + kc);
        uint32_t al2 = lds_u32(al_base + kc + 8);
        uint32_t al3 = lds_u32(al_base + 8 * RS + kc + 8);
        #pragma unroll
        for (int nb = 0; nb < 16; nb++) {
            const __half* bp = F + (nb * 8 + g) * RS + kc;
            uint32_t b0 = lds_u32(bp);
            uint32_t b1 = lds_u32(bp + 8);
            mma16816(acc[nb], ah0, ah1, ah2, ah3, b0, b1);
            mma16816(acc[nb], al0, al1, al2, al3, b0, b1);
        }
    }

    // ---- store: D[row][col], row = warp*16 + g(+8), col = nb*8 + 2tg(+1) ----
    float* op = out + (size_t)tile * (TILE_M * D) + (size_t)(warp * 16) * D;
    #pragma unroll
    for (int nb = 0; nb < 16; nb++) {
        int col = nb * 8 + 2 * tg;
        float2 v0 = make_float2(acc[nb][0], acc[nb][1]);
        float2 v1 = make_float2(acc[nb][2], acc[nb][3]);
        __stcs(reinterpret_cast<float2*>(op + (size_t)g * D + col), v0);
        __stcs(reinterpret_cast<float2*>(op + (size_t)(g + 8) * D + col), v1);
    }
}

// ======================= Harness entry =======================

extern "C" void kernel_launch(void* const* d_in, const int* in_sizes, int n_in,
                              void* d_out, int out_size) {
    const float* x  = (const float*)d_in[0];
    const float* br = (const float*)d_in[3];
    const float* bi = (const float*)d_in[4];
    float* out = (float*)d_out;

    int rows   = in_sizes[0] / D;       // 262144
    int ntiles = rows / TILE_M;         // 2048

    fourier_prep<<<1, 128>>>(br, bi);

    cudaFuncSetAttribute(fourier_main, cudaFuncAttributeMaxDynamicSharedMemorySize,
                         SMEM_TOTAL);
    fourier_main<<<ntiles, 256, SMEM_TOTAL>>>(x, out);
}

// round 5
// speedup vs baseline: 1.1892x; 1.1892x over previous
#include <cuda_runtime.h>
#include <cuda_fp16.h>
#include <cstdint>
#include <cstddef>

#define DINLINE __device__ __forceinline__

// =====================================================================
// out[m][n] = sum_k x[m][k] * h[(n-k) & 127],   h = Re(ifft(b))
// Single-pass fp16 GEMM:
//   A = fp16(x) tile [128 x 128], B = F[n][k] = fp16(h[(n-k)&127])
//   mma.sync.aligned.m16n8k16.row.col.f32.f16.f16.f32
// Error = fp16(x) + fp16(h) rounding ~= 3e-4 << 1e-3 gate.
// =====================================================================

static constexpr int D = 128;
static constexpr int TILE_M = 128;
// padded fp16 row stride: 136 halfs = 272 bytes (conflict-free LDS/ldmatrix)
static constexpr int RS = 136;
static constexpr int TILE_BYTES = 128 * RS * 2;     // 34816
static constexpr int F_OFF  = 0;
static constexpr int XH_OFF = TILE_BYTES;           // 34816
static constexpr int SMEM_TOTAL = 2 * TILE_BYTES;   // 69632 -> 3 CTAs/SM

__device__ unsigned short g_h[128];   // fp16 bits of h

// ======================= Prep kernel: h = Re(ifft(b)) =======================

__global__ void __launch_bounds__(128) fourier_prep(const float* __restrict__ br,
                                                    const float* __restrict__ bi) {
    __shared__ float ct[128], st[128], sbr[128], sbi[128];
    int t = threadIdx.x;
    float ang = (float)t * (6.28318530717958647692f / 128.0f);
    float s, c;
    sincosf(ang, &s, &c);
    ct[t] = c; st[t] = s;
    sbr[t] = br[t]; sbi[t] = bi[t];
    __syncthreads();
    float acc = 0.0f;
    #pragma unroll 8
    for (int k = 0; k < 128; k++) {
        int idx = (k * t) & 127;             // exact integer angle reduction
        acc = fmaf(sbr[k], ct[idx], acc);
        acc = fmaf(-sbi[k], st[idx], acc);
    }
    acc *= (1.0f / 128.0f);
    g_h[t] = __half_as_ushort(__float2half_rn(acc));
}

// ======================= PTX wrappers =======================

DINLINE void mma16816(float* d, uint32_t a0, uint32_t a1, uint32_t a2, uint32_t a3,
                      uint32_t b0, uint32_t b1) {
    asm volatile(
        "mma.sync.aligned.m16n8k16.row.col.f32.f16.f16.f32 "
        "{%0,%1,%2,%3}, {%4,%5,%6,%7}, {%8,%9}, {%0,%1,%2,%3};"
        : "+f"(d[0]), "+f"(d[1]), "+f"(d[2]), "+f"(d[3])
        : "r"(a0), "r"(a1), "r"(a2), "r"(a3), "r"(b0), "r"(b1));
}

DINLINE void ldmatrix_x4(uint32_t& r0, uint32_t& r1, uint32_t& r2, uint32_t& r3,
                         uint32_t addr) {
    asm volatile("ldmatrix.sync.aligned.m8n8.x4.shared.b16 {%0,%1,%2,%3}, [%4];"
                 : "=r"(r0), "=r"(r1), "=r"(r2), "=r"(r3) : "r"(addr));
}

// ======================= Main kernel =======================

__global__ void __launch_bounds__(256, 3)
fourier_main(const float* __restrict__ x, float* __restrict__ out) {
    extern __shared__ char smem[];
    __half* F  = reinterpret_cast<__half*>(smem + F_OFF);
    __half* XH = reinterpret_cast<__half*>(smem + XH_OFF);

    const int tid  = threadIdx.x;
    const int warp = tid >> 5;
    const int lane = tid & 31;
    const int tile = blockIdx.x;

    const float4* src = reinterpret_cast<const float4*>(x) + (size_t)tile * 4096;

    // ---- batch 1: issue 8 LDG.128 (in flight while building F) ----
    float4 v[8];
    #pragma unroll
    for (int it = 0; it < 8; it++)
        v[it] = __ldcs(src + it * 256 + tid);

    // ---- build filter tile F[n][k] = h[(n-k)&127] ----
    #pragma unroll
    for (int idx = tid; idx < 128 * 64; idx += 256) {
        int n  = idx >> 6;
        int k  = (idx & 63) << 1;
        uint32_t w = (uint32_t)g_h[(n - k) & 127]
                   | ((uint32_t)g_h[(n - k - 1) & 127] << 16);
        *reinterpret_cast<uint32_t*>(F + n * RS + k) = w;
    }

    // ---- convert batch 1 to fp16, store to smem ----
    #pragma unroll
    for (int it = 0; it < 8; it++) {
        int i4 = it * 256 + tid;
        int row = i4 >> 5;              // 32 float4 per 128-float row
        int col = (i4 & 31) << 2;
        __half2* ph = reinterpret_cast<__half2*>(XH + row * RS + col);
        ph[0] = __float22half2_rn(make_float2(v[it].x, v[it].y));
        ph[1] = __float22half2_rn(make_float2(v[it].z, v[it].w));
    }

    // ---- batch 2 ----
    #pragma unroll
    for (int it = 0; it < 8; it++)
        v[it] = __ldcs(src + (it + 8) * 256 + tid);
    #pragma unroll
    for (int it = 0; it < 8; it++) {
        int i4 = (it + 8) * 256 + tid;
        int row = i4 >> 5;
        int col = (i4 & 31) << 2;
        __half2* ph = reinterpret_cast<__half2*>(XH + row * RS + col);
        ph[0] = __float22half2_rn(make_float2(v[it].x, v[it].y));
        ph[1] = __float22half2_rn(make_float2(v[it].z, v[it].w));
    }
    __syncthreads();

    // ---- ldmatrix addresses ----
    const int r = lane & 7;
    const int q = lane >> 3;           // quad: which 8x8 matrix this lane feeds
    const int g  = lane >> 2;
    const int tg = lane & 3;

    // A: 16x16 tile at (warp*16, ks*16); quads map {rows0-7,k0-7},{rows8-15,k0-7},
    //    {rows0-7,k8-15},{rows8-15,k8-15}
    uint32_t a_addr = (uint32_t)__cvta_generic_to_shared(
        XH + ((size_t)(warp * 16 + (q & 1) * 8 + r)) * RS + (q >> 1) * 8);
    // B: two n-blocks per x4; quads map {nb0,k0-7},{nb0,k8-15},{nb1,k0-7},{nb1,k8-15}
    uint32_t b_addr = (uint32_t)__cvta_generic_to_shared(
        F + ((size_t)((q >> 1) * 8 + r)) * RS + (q & 1) * 8);

    // ---- hoist all A fragments (8 ks * 4 regs = 32 regs) ----
    uint32_t a[8][4];
    #pragma unroll
    for (int ks = 0; ks < 8; ks++)
        ldmatrix_x4(a[ks][0], a[ks][1], a[ks][2], a[ks][3], a_addr + ks * 32);

    // ---- main loop: 8 nb-pairs; per pair: 8 ldmatrix.x4, 16 MMAs, store ----
    float* op = out + (size_t)tile * (TILE_M * D) + (size_t)(warp * 16) * D;
    #pragma unroll
    for (int nbp = 0; nbp < 8; nbp++) {
        float acc0[4] = {0.f, 0.f, 0.f, 0.f};
        float acc1[4] = {0.f, 0.f, 0.f, 0.f};
        uint32_t bb = b_addr + (uint32_t)(nbp * 16 * RS * 2);
        #pragma unroll
        for (int ks = 0; ks < 8; ks++) {
            uint32_t b0, b1, b2, b3;
            ldmatrix_x4(b0, b1, b2, b3, bb + ks * 32);
            mma16816(acc0, a[ks][0], a[ks][1], a[ks][2], a[ks][3], b0, b1);
            mma16816(acc1, a[ks][0], a[ks][1], a[ks][2], a[ks][3], b2, b3);
        }
        int col0 = nbp * 16 + 2 * tg;
        __stcs(reinterpret_cast<float2*>(op + (size_t)g * D + col0),
               make_float2(acc0[0], acc0[1]));
        __stcs(reinterpret_cast<float2*>(op + (size_t)(g + 8) * D + col0),
               make_float2(acc0[2], acc0[3]));
        __stcs(reinterpret_cast<float2*>(op + (size_t)g * D + col0 + 8),
               make_float2(acc1[0], acc1[1]));
        __stcs(reinterpret_cast<float2*>(op + (size_t)(g + 8) * D + col0 + 8),
               make_float2(acc1[2], acc1[3]));
    }
}

// ======================= Harness entry =======================

extern "C" void kernel_launch(void* const* d_in, const int* in_sizes, int n_in,
                              void* d_out, int out_size) {
    const float* x  = (const float*)d_in[0];
    const float* br = (const float*)d_in[3];
    const float* bi = (const float*)d_in[4];
    float* out = (float*)d_out;

    int rows   = in_sizes[0] / D;       // 262144
    int ntiles = rows / TILE_M;         // 2048

    fourier_prep<<<1, 128>>>(br, bi);

    cudaFuncSetAttribute(fourier_main, cudaFuncAttributeMaxDynamicSharedMemorySize,
                         SMEM_TOTAL);
    fourier_main<<<ntiles, 256, SMEM_TOTAL>>>(x, out);
}

// round 7
// speedup vs baseline: 1.5172x; 1.2759x over previous
#include <cuda_runtime.h>
#include <cuda_fp16.h>
#include <cstdint>
#include <cstddef>

#define DINLINE __device__ __forceinline__

// =====================================================================
// out[m][n] = sum_k x[m][k] * h[(n-k) & 127],   h = Re(ifft(b))
// Single-pass fp16 GEMM via mma.sync m16n8k16.
// Circulant trick: the 16x16 B fragment at (nbp, ks) depends only on
// d = (nbp - ks) & 7  ->  only 8 distinct B fragments, hoisted in regs.
// Column-permuted F so the epilogue is st.v4.f32 (coalesced 16B/lane).
// =====================================================================

static constexpr int D = 128;
static constexpr int TILE_M = 128;
static constexpr int RS  = 136;  // x tile row stride (halves), conflict-free
static constexpr int RSF = 24;   // F tile row stride (halves), conflict-free
static constexpr int F_BYTES = 128 * RSF * 2;        // 6144
static constexpr int F_OFF  = 0;
static constexpr int XH_OFF = F_BYTES;               // 6144
static constexpr int SMEM_TOTAL = XH_OFF + 128 * RS * 2;  // 40960 -> 3 CTAs/SM

__device__ unsigned short g_h[128];   // fp16 bits of h

// ======================= Prep kernel: h = Re(ifft(b)) =======================

__global__ void __launch_bounds__(128) fourier_prep(const float* __restrict__ br,
                                                    const float* __restrict__ bi) {
    __shared__ float ct[128], st[128], sbr[128], sbi[128];
    int t = threadIdx.x;
    float ang = (float)t * (6.28318530717958647692f / 128.0f);
    float s, c;
    sincosf(ang, &s, &c);
    ct[t] = c; st[t] = s;
    sbr[t] = br[t]; sbi[t] = bi[t];
    __syncthreads();
    float acc = 0.0f;
    #pragma unroll 8
    for (int k = 0; k < 128; k++) {
        int idx = (k * t) & 127;             // exact integer angle reduction
        acc = fmaf(sbr[k], ct[idx], acc);
        acc = fmaf(-sbi[k], st[idx], acc);
    }
    acc *= (1.0f / 128.0f);
    g_h[t] = __half_as_ushort(__float2half_rn(acc));
}

// ======================= PTX wrappers =======================

DINLINE void mma16816(float* d, uint32_t a0, uint32_t a1, uint32_t a2, uint32_t a3,
                      uint32_t b0, uint32_t b1) {
    asm volatile(
        "mma.sync.aligned.m16n8k16.row.col.f32.f16.f16.f32 "
        "{%0,%1,%2,%3}, {%4,%5,%6,%7}, {%8,%9}, {%0,%1,%2,%3};"
        : "+f"(d[0]), "+f"(d[1]), "+f"(d[2]), "+f"(d[3])
        : "r"(a0), "r"(a1), "r"(a2), "r"(a3), "r"(b0), "r"(b1));
}

DINLINE void ldmatrix_x4(uint32_t& r0, uint32_t& r1, uint32_t& r2, uint32_t& r3,
                         uint32_t addr) {
    asm volatile("ldmatrix.sync.aligned.m8n8.x4.shared.b16 {%0,%1,%2,%3}, [%4];"
                 : "=r"(r0), "=r"(r1), "=r"(r2), "=r"(r3) : "r"(addr));
}

// column permutation within a 16-group: j -> output column offset
DINLINE int colmap(int j) {
    return (j < 8) ? (((j >> 1) << 2) | (j & 1))
                   : ((((j - 8) >> 1) << 2) | 2 | (j & 1));
}

// ======================= Main kernel =======================

__global__ void __launch_bounds__(256, 3)
fourier_main(const float* __restrict__ x, float* __restrict__ out) {
    extern __shared__ char smem[];
    __half* F  = reinterpret_cast<__half*>(smem + F_OFF);
    __half* XH = reinterpret_cast<__half*>(smem + XH_OFF);

    const int tid  = threadIdx.x;
    const int warp = tid >> 5;
    const int lane = tid & 31;
    const int tile = blockIdx.x;

    const float4* src = reinterpret_cast<const float4*>(x) + (size_t)tile * 4096;

    // ---- batch 1: 8 LDG.128 in flight while building F ----
    float4 v[8];
    #pragma unroll
    for (int it = 0; it < 8; it++)
        v[it] = __ldcs(src + it * 256 + tid);

    // ---- build F[n'][k] = h[(perm(n') - k) & 127], k in [0,16) only ----
    // n' = d*16 + j ; perm(n') = d*16 + colmap(j)
    #pragma unroll
    for (int u = 0; u < 4; u++) {
        int idx = u * 256 + tid;           // 128 rows x 8 u32 cols
        int n  = idx >> 3;
        int k  = (idx & 7) << 1;
        int pn = (n & ~15) + colmap(n & 15);
        uint32_t w = (uint32_t)g_h[(pn - k) & 127]
                   | ((uint32_t)g_h[(pn - k - 1) & 127] << 16);
        *reinterpret_cast<uint32_t*>(F + n * RSF + k) = w;
    }

    // ---- convert batch 1, store to smem ----
    #pragma unroll
    for (int it = 0; it < 8; it++) {
        int i4 = it * 256 + tid;
        int row = i4 >> 5;
        int col = (i4 & 31) << 2;
        __half2* ph = reinterpret_cast<__half2*>(XH + row * RS + col);
        ph[0] = __float22half2_rn(make_float2(v[it].x, v[it].y));
        ph[1] = __float22half2_rn(make_float2(v[it].z, v[it].w));
    }

    // ---- batch 2 ----
    #pragma unroll
    for (int it = 0; it < 8; it++)
        v[it] = __ldcs(src + (it + 8) * 256 + tid);
    #pragma unroll
    for (int it = 0; it < 8; it++) {
        int i4 = (it + 8) * 256 + tid;
        int row = i4 >> 5;
        int col = (i4 & 31) << 2;
        __half2* ph = reinterpret_cast<__half2*>(XH + row * RS + col);
        ph[0] = __float22half2_rn(make_float2(v[it].x, v[it].y));
        ph[1] = __float22half2_rn(make_float2(v[it].z, v[it].w));
    }
    __syncthreads();

    // ---- fragment addresses ----
    const int r  = lane & 7;
    const int q  = lane >> 3;
    const int g  = lane >> 2;
    const int tg = lane & 3;

    // A quads: {rows 0-7,k0-7},{rows 8-15,k0-7},{rows 0-7,k8-15},{rows 8-15,k8-15}
    uint32_t a_addr = (uint32_t)__cvta_generic_to_shared(
        XH + ((size_t)(warp * 16 + (q & 1) * 8 + r)) * RS + (q >> 1) * 8);
    // B quads: {j0-7,k0-7},{j0-7,k8-15},{j8-15,k0-7},{j8-15,k8-15}
    uint32_t b_addr = (uint32_t)__cvta_generic_to_shared(
        F + ((size_t)((q >> 1) * 8 + r)) * RSF + (q & 1) * 8);

    // ---- hoist A (8 ks) and B (8 diagonals d) fragments: 64 regs ----
    uint32_t a[8][4], b[8][4];
    #pragma unroll
    for (int ks = 0; ks < 8; ks++)
        ldmatrix_x4(a[ks][0], a[ks][1], a[ks][2], a[ks][3], a_addr + ks * 32);
    #pragma unroll
    for (int d = 0; d < 8; d++)
        ldmatrix_x4(b[d][0], b[d][1], b[d][2], b[d][3],
                    b_addr + (uint32_t)(d * 16 * RSF * 2));

    // ---- mainloop: zero smem traffic; 128 MMAs + 16 coalesced STG.128 ----
    float* op = out + (size_t)tile * (TILE_M * D) + (size_t)(warp * 16) * D;
    #pragma unroll
    for (int nbp = 0; nbp < 8; nbp++) {
        float acc0[4] = {0.f, 0.f, 0.f, 0.f};
        float acc1[4] = {0.f, 0.f, 0.f, 0.f};
        #pragma unroll
        for (int ks = 0; ks < 8; ks++) {
            const uint32_t* bd = b[(nbp - ks) & 7];
            mma16816(acc0, a[ks][0], a[ks][1], a[ks][2], a[ks][3], bd[0], bd[1]);
            mma16816(acc1, a[ks][0], a[ks][1], a[ks][2], a[ks][3], bd[2], bd[3]);
        }
        // thread (g,tg): cols {4tg,4tg+1} from acc0, {4tg+2,4tg+3} from acc1
        int col0 = nbp * 16 + 4 * tg;
        __stcs(reinterpret_cast<float4*>(op + (size_t)g * D + col0),
               make_float4(acc0[0], acc0[1], acc1[0], acc1[1]));
        __stcs(reinterpret_cast<float4*>(op + (size_t)(g + 8) * D + col0),
               make_float4(acc0[2], acc0[3], acc1[2], acc1[3]));
    }
}

// ======================= Harness entry =======================

extern "C" void kernel_launch(void* const* d_in, const int* in_sizes, int n_in,
                              void* d_out, int out_size) {
    const float* x  = (const float*)d_in[0];
    const float* br = (const float*)d_in[3];
    const float* bi = (const float*)d_in[4];
    float* out = (float*)d_out;

    int rows   = in_sizes[0] / D;       // 262144
    int ntiles = rows / TILE_M;         // 2048

    fourier_prep<<<1, 128>>>(br, bi);

    cudaFuncSetAttribute(fourier_main, cudaFuncAttributeMaxDynamicSharedMemorySize,
                         SMEM_TOTAL);
    fourier_main<<<ntiles, 256, SMEM_TOTAL>>>(x, out);
}